// round 1
// baseline (speedup 1.0000x reference)
#include <cuda_runtime.h>

// CrossAttention shortcut:
//   Keys/values are projected from visual_features [B,C] and broadcast over T,
//   so softmax over the key axis is exactly uniform and y == v for every query.
//   out[b,t,:] = ((vf[b] @ Wv + bv) @ Wp + bp)   (independent of t, x, Wq, Wk)
//
// Pipeline (3 kernels, deterministic fixed-order split-K reductions):
//   1) gemm1:  part1[ks][b][c] = sum_{k in chunk ks} vf[b,k] * Wv[k,c]
//   2) gemm2:  reduce part1 -> vv chunk (smem), part2[ks][b][c] = vv_chunk @ Wp_chunk
//   3) bcast:  r[b][c] = bp[c] + sum_ks part2[ks][b][c]; write r to all T rows

#define B_ 4
#define T_ 1024
#define C_ 1024
#define KS_ 32      // number of split-K chunks
#define KCH_ 32     // k elements per chunk (KS_*KCH_ == C_)
#define TT_ 16      // T rows per broadcast block

// Split-K partial buffers (no cudaMalloc allowed): 2 * 512 KB.
__device__ float g_part1[KS_ * B_ * C_];
__device__ float g_part2[KS_ * B_ * C_];

// ---------------------------------------------------------------------------
// Kernel 1: partial GEMM  vf[B,C] @ Wv[C,C]  (split-K, no bias yet)
// grid (1, KS_, B_), block 256 (each thread owns 4 consecutive columns)
// ---------------------------------------------------------------------------
__global__ void ca_gemm1(const float* __restrict__ vf,
                         const float* __restrict__ Wv) {
    const int b  = blockIdx.z;
    const int ks = blockIdx.y;
    const int c4 = threadIdx.x * 4;
    const int k0 = ks * KCH_;

    float4 acc = make_float4(0.f, 0.f, 0.f, 0.f);
#pragma unroll 8
    for (int kk = 0; kk < KCH_; kk++) {
        const float a = __ldg(&vf[b * C_ + k0 + kk]);
        const float4 w =
            *reinterpret_cast<const float4*>(&Wv[(k0 + kk) * C_ + c4]);
        acc.x += a * w.x;
        acc.y += a * w.y;
        acc.z += a * w.z;
        acc.w += a * w.w;
    }
    *reinterpret_cast<float4*>(&g_part1[(ks * B_ + b) * C_ + c4]) = acc;
}

// ---------------------------------------------------------------------------
// Kernel 2: reduce part1 for this block's k-chunk (fixed order), add bv,
//           then partial GEMM  vv[B,C] @ Wp[C,C]
// grid (1, KS_, B_), block 256
// ---------------------------------------------------------------------------
__global__ void ca_gemm2(const float* __restrict__ bv,
                         const float* __restrict__ Wp) {
    __shared__ float s_vv[KCH_];
    const int b  = blockIdx.z;
    const int ks = blockIdx.y;
    const int k0 = ks * KCH_;
    const int tid = threadIdx.x;

    if (tid < KCH_) {
        float s = __ldg(&bv[k0 + tid]);
#pragma unroll
        for (int p = 0; p < KS_; p++)
            s += g_part1[(p * B_ + b) * C_ + k0 + tid];
        s_vv[tid] = s;
    }
    __syncthreads();

    const int c4 = tid * 4;
    float4 acc = make_float4(0.f, 0.f, 0.f, 0.f);
#pragma unroll 8
    for (int kk = 0; kk < KCH_; kk++) {
        const float a = s_vv[kk];
        const float4 w =
            *reinterpret_cast<const float4*>(&Wp[(k0 + kk) * C_ + c4]);
        acc.x += a * w.x;
        acc.y += a * w.y;
        acc.z += a * w.z;
        acc.w += a * w.w;
    }
    *reinterpret_cast<float4*>(&g_part2[(ks * B_ + b) * C_ + c4]) = acc;
}

// ---------------------------------------------------------------------------
// Kernel 3: reduce part2 (fixed order) + bp, broadcast to TT_ rows of out
// grid (1, T_/TT_, B_), block 256
// ---------------------------------------------------------------------------
__global__ void ca_bcast(const float* __restrict__ bp,
                         float* __restrict__ out) {
    const int b  = blockIdx.z;
    const int t0 = blockIdx.y * TT_;
    const int c4 = threadIdx.x * 4;

    float4 r = *reinterpret_cast<const float4*>(&bp[c4]);
#pragma unroll
    for (int p = 0; p < KS_; p++) {
        const float4 v =
            *reinterpret_cast<const float4*>(&g_part2[(p * B_ + b) * C_ + c4]);
        r.x += v.x;
        r.y += v.y;
        r.z += v.z;
        r.w += v.w;
    }

#pragma unroll
    for (int t = 0; t < TT_; t++) {
        *reinterpret_cast<float4*>(&out[((b * T_) + t0 + t) * C_ + c4]) = r;
    }
}

// ---------------------------------------------------------------------------
// Input order (metadata): 0 x, 1 visual_features, 2 Wq, 3 bq, 4 Wk, 5 bk,
//                         6 Wv, 7 bv, 8 Wp, 9 bp
// ---------------------------------------------------------------------------
extern "C" void kernel_launch(void* const* d_in, const int* in_sizes, int n_in,
                              void* d_out, int out_size) {
    const float* vf = (const float*)d_in[1];
    const float* Wv = (const float*)d_in[6];
    const float* bv = (const float*)d_in[7];
    const float* Wp = (const float*)d_in[8];
    const float* bp = (const float*)d_in[9];
    float* out = (float*)d_out;

    ca_gemm1<<<dim3(1, KS_, B_), 256>>>(vf, Wv);
    ca_gemm2<<<dim3(1, KS_, B_), 256>>>(bv, Wp);
    ca_bcast<<<dim3(1, T_ / TT_, B_), 256>>>(bp, out);
}